// round 15
// baseline (speedup 1.0000x reference)
#include <cuda_runtime.h>
#include <cuda_bf16.h>

// RepeatLayers: variable-length repeat_interleave along axis 0.
//   encoder_h: [N=8192, D=1024] fp32
//   repeats:   [N] int32 in [0, 8)
//   out:       [sum(repeats), D] fp32
//
// R15 = R14 with the launch shape fixed for single-wave execution:
//   - occ target 8 (1184 slots >= 1024 CTAs -> ONE wave, no 136-CTA tail
//     wave that occ-6 suffered: 1024 = 888 + 136).
//   - regs <= 32 by giving group-A and group-B row data DISJOINT live ranges
//     (B rows loaded after A stores are issued; ptxas reuses the registers)
//     and computing offsets incrementally (no off[8] array).
// Everything else (L2 evict hints, REDUX reductions, RPC=8, grid 1024)
// unchanged from R14.

#define N_ROWS 8192
#define D_ELEMS 1024
#define D_VEC4 (D_ELEMS / 4)     // 256 float4 per row
#define ROWS_PER_CTA 8
#define NB_CTAS (N_ROWS / ROWS_PER_CTA)   // 1024

// ---- L2 policy helpers ----
__device__ __forceinline__ float4 ldg_evict_last(const float4* p) {
    float4 v;
    asm volatile(
        "{\n\t"
        ".reg .b64 pol;\n\t"
        "createpolicy.fractional.L2::evict_last.b64 pol, 1.0;\n\t"
        "ld.global.nc.L2::cache_hint.v4.f32 {%0,%1,%2,%3}, [%4], pol;\n\t"
        "}"
        : "=f"(v.x), "=f"(v.y), "=f"(v.z), "=f"(v.w) : "l"(p));
    return v;
}
__device__ __forceinline__ void stg_evict_first(float4* p, float4 v) {
    asm volatile(
        "{\n\t"
        ".reg .b64 pol;\n\t"
        "createpolicy.fractional.L2::evict_first.b64 pol, 1.0;\n\t"
        "st.global.L2::cache_hint.v4.f32 [%0], {%1,%2,%3,%4}, pol;\n\t"
        "}"
        :: "l"(p), "f"(v.x), "f"(v.y), "f"(v.z), "f"(v.w) : "memory");
}

__global__ __launch_bounds__(256, 8)
void repeat_fused_kernel(const float* __restrict__ src,
                         const int* __restrict__ repeats,
                         float* __restrict__ out) {
    const int t = threadIdx.x;                    // 0..255
    const int lane = t & 31;
    const int wid = t >> 5;
    const int b = blockIdx.x;
    const int row0 = b * ROWS_PER_CTA;            // first of this CTA's 8 rows

    const int4* rp = reinterpret_cast<const int4*>(repeats);

    // --- This CTA's 8 repeat counts ---
    const int4 ra = __ldg(&rp[2 * b]);
    const int4 rb = __ldg(&rp[2 * b + 1]);

    // --- Front-batch group A row loads (rows 0..3), evict_last ---
    const float4* srcv = reinterpret_cast<const float4*>(src);
    float4 va[4];
    if (ra.x > 0) va[0] = ldg_evict_last(srcv + (size_t)(row0 + 0) * D_VEC4 + t);
    if (ra.y > 0) va[1] = ldg_evict_last(srcv + (size_t)(row0 + 1) * D_VEC4 + t);
    if (ra.z > 0) va[2] = ldg_evict_last(srcv + (size_t)(row0 + 2) * D_VEC4 + t);
    if (ra.w > 0) va[3] = ldg_evict_last(srcv + (size_t)(row0 + 3) * D_VEC4 + t);

    // --- Cooperative prefix sum: off0 = sum(repeats[0..row0)) ---
    const int n4 = row0 >> 2;                     // 2*b int4 words
    int sum = 0;
    for (int i = t; i < n4; i += 256) {
        int4 a = __ldg(&rp[i]);
        sum += a.x + a.y + a.z + a.w;
    }
    sum = __reduce_add_sync(0xFFFFFFFFu, sum);

    __shared__ int wsum[8];
    if (lane == 0) wsum[wid] = sum;
    __syncthreads();
    int cur;
    {
        int s2 = (lane < 8) ? wsum[lane] : 0;
        cur = __reduce_add_sync(0xFFFFFFFFu, s2);   // off0, running offset
    }

    float4* outv = reinterpret_cast<float4*>(out);

    // --- Store group A (incremental offsets) ---
    {
        const int repA[4] = {ra.x, ra.y, ra.z, ra.w};
#pragma unroll
        for (int i = 0; i < 4; i++) {
            float4* o = outv + (size_t)cur * D_VEC4 + t;
#pragma unroll 8
            for (int r = 0; r < repA[i]; r++) {
                stg_evict_first(o, va[i]);
                o += D_VEC4;
            }
            cur += repA[i];
        }
    }

    // --- Group B (rows 4..7): load after A's register lifetime ends ---
    {
        float4 vb[4];
        if (rb.x > 0) vb[0] = ldg_evict_last(srcv + (size_t)(row0 + 4) * D_VEC4 + t);
        if (rb.y > 0) vb[1] = ldg_evict_last(srcv + (size_t)(row0 + 5) * D_VEC4 + t);
        if (rb.z > 0) vb[2] = ldg_evict_last(srcv + (size_t)(row0 + 6) * D_VEC4 + t);
        if (rb.w > 0) vb[3] = ldg_evict_last(srcv + (size_t)(row0 + 7) * D_VEC4 + t);

        const int repB[4] = {rb.x, rb.y, rb.z, rb.w};
#pragma unroll
        for (int i = 0; i < 4; i++) {
            float4* o = outv + (size_t)cur * D_VEC4 + t;
#pragma unroll 8
            for (int r = 0; r < repB[i]; r++) {
                stg_evict_first(o, vb[i]);
                o += D_VEC4;
            }
            cur += repB[i];
        }
    }
}

extern "C" void kernel_launch(void* const* d_in, const int* in_sizes, int n_in,
                              void* d_out, int out_size) {
    const float* encoder_h;
    const int* repeats;
    if (in_sizes[0] == N_ROWS * D_ELEMS) {
        encoder_h = (const float*)d_in[0];
        repeats   = (const int*)d_in[1];
    } else {
        encoder_h = (const float*)d_in[1];
        repeats   = (const int*)d_in[0];
    }
    float* out = (float*)d_out;
    (void)n_in; (void)out_size;

    repeat_fused_kernel<<<NB_CTAS, 256>>>(encoder_h, repeats, out);
}